// round 15
// baseline (speedup 1.0000x reference)
#include <cuda_runtime.h>
#include <cuda_fp16.h>
#include <cstdint>

// Problem constants
#define NB   64
#define NH   32
#define NW   32
#define ND   384
#define NBHW (NB*NH*NW)          // 65536 rows

// Scratch (device globals; no allocation allowed)
__device__ __half g_Yhw_h[(size_t)NBHW * ND];   // Yh + Yw (fp16)
__device__ __half g_xh[(size_t)NBHW * ND];      // fp16 copy of x
__device__ __half g_Wo_h[ND * ND];              // fp16 Wo
__device__ __half g_Wco_h[ND * ND];             // fp16 (Wo @ Wc)
__device__ float  g_bias[ND];                   // Wo @ bc + bo

static __device__ __forceinline__ uint32_t s2u(const void* p) {
    uint32_t a;
    asm("{ .reg .u64 t; cvta.to.shared.u64 t, %1; cvt.u32.u64 %0, t; }" : "=r"(a) : "l"(p));
    return a;
}
static __device__ __forceinline__ void cp16(uint32_t dst, const void* src) {
    asm volatile("cp.async.cg.shared.global [%0], [%1], 16;" :: "r"(dst), "l"(src));
}
static __device__ __forceinline__ uint32_t f2tf(float f) {
    uint32_t r;
    asm("cvt.rna.tf32.f32 %0, %1;" : "=r"(r) : "f"(f));
    return r;
}
static __device__ __forceinline__ void mma1688(float* d, const uint32_t* a, const uint32_t* b) {
    asm volatile(
        "mma.sync.aligned.m16n8k8.row.col.f32.tf32.tf32.f32 "
        "{%0,%1,%2,%3},{%4,%5,%6,%7},{%8,%9},{%0,%1,%2,%3};"
        : "+f"(d[0]), "+f"(d[1]), "+f"(d[2]), "+f"(d[3])
        : "r"(a[0]), "r"(a[1]), "r"(a[2]), "r"(a[3]), "r"(b[0]), "r"(b[1]));
}
static __device__ __forceinline__ void mma16816(float* d, const uint32_t* a, const uint32_t* b) {
    asm volatile(
        "mma.sync.aligned.m16n8k16.row.col.f32.f16.f16.f32 "
        "{%0,%1,%2,%3},{%4,%5,%6,%7},{%8,%9},{%0,%1,%2,%3};"
        : "+f"(d[0]), "+f"(d[1]), "+f"(d[2]), "+f"(d[3])
        : "r"(a[0]), "r"(a[1]), "r"(a[2]), "r"(a[3]), "r"(b[0]), "r"(b[1]));
}

// ---------------------------------------------------------------------------
// Wco[o][d] = sum_k Wo[o][k] * Wc[k][d]  (stored fp16)
__global__ void wco_kernel(const float* __restrict__ Wo, const float* __restrict__ Wc) {
    __shared__ float As[16][16];
    __shared__ float Bs[16][17];
    int o = blockIdx.y * 16 + threadIdx.y;
    int d = blockIdx.x * 16 + threadIdx.x;
    float acc = 0.f;
    for (int k0 = 0; k0 < ND; k0 += 16) {
        As[threadIdx.y][threadIdx.x] = Wo[o * ND + k0 + threadIdx.x];
        Bs[threadIdx.y][threadIdx.x] = Wc[(k0 + threadIdx.y) * ND + d];
        __syncthreads();
#pragma unroll
        for (int k = 0; k < 16; k++) acc += As[threadIdx.y][k] * Bs[k][threadIdx.x];
        __syncthreads();
    }
    g_Wco_h[o * ND + d] = __float2half(acc);
}

// bias[o] = bo[o] + sum_k Wo[o][k]*bc[k] — one warp per output element.
__global__ void bias_kernel(const float* __restrict__ Wo, const float* __restrict__ bc,
                            const float* __restrict__ bo) {
    int warp = threadIdx.x >> 5, lane = threadIdx.x & 31;
    int o = blockIdx.x * 32 + warp;
    float s = 0.f;
#pragma unroll
    for (int q = 0; q < 12; q++)
        s += Wo[o * ND + lane + 32 * q] * bc[lane + 32 * q];
#pragma unroll
    for (int off = 16; off; off >>= 1) s += __shfl_xor_sync(~0u, s, off);
    if (lane == 0) g_bias[o] = s + bo[o];
}

// Wo -> fp16
__global__ void convw_kernel(const float* __restrict__ Wo) {
    int idx = blockIdx.x * 1024 + threadIdx.x;
    g_Wo_h[idx] = __float2half(Wo[idx]);
}

// ---------------------------------------------------------------------------
// Fully fused mixer pass: projection + grouped-mix logits + softmax + tensor-core apply.
// which=0 (w-mix): block (b, h=s): rows j = w, x[b,s,j,:]; writes Yhw_h; also emits g_xh.
// which=1 (h-mix): block (b, w=s): rows j = h, x[b,j,s,:]; accumulates into Yhw_h.
// smem floats: sX[32][388] | sW1[768] | sY[64] | sZ[32][36]
#define SXST  388
#define SZST  36
#define MX_SX   0
#define MX_SW1  (32 * SXST)
#define MX_SY   (MX_SW1 + 768)
#define MX_SZ   (MX_SY + 64)
#define MX_DYN  ((MX_SZ + 32 * SZST) * 4)   // 57,600 bytes

__global__ __launch_bounds__(384, 2) void mix_fused_kernel(
    const float* __restrict__ x, const float* __restrict__ W1,
    const float* __restrict__ b1, const float* __restrict__ W2,
    const float* __restrict__ b2, int which) {
    extern __shared__ float sm[];
    float* sX  = sm + MX_SX;
    float* sW1 = sm + MX_SW1;
    float* sY  = sm + MX_SY;
    float* sZ  = sm + MX_SZ;

    int tid = threadIdx.x;
    int blk = blockIdx.x;
    int b = blk >> 5, s = blk & 31;
    int warp = tid >> 5, lane = tid & 31;
    int g = lane >> 2, c = lane & 3;
    int dbase = warp * 32;                   // this warp's 32 output columns

    __half* ybase;
    size_t ostride;
    if (which) { ybase = g_Yhw_h + ((size_t)b * 1024 + s) * ND; ostride = (size_t)32 * ND; }
    else       { ybase = g_Yhw_h + (size_t)blk * (32 * ND);     ostride = (size_t)ND; }

    // MMA accumulators; which=1 preloads its RMW values now (latency hidden
    // behind staging / proj / softmax below).
    float acc[2][4][4];
#pragma unroll
    for (int mi = 0; mi < 2; mi++)
#pragma unroll
        for (int ni = 0; ni < 4; ni++) {
            if (which) {
                int col = dbase + ni * 8 + 2 * c;
                __half2 u0 = *(const __half2*)(ybase + (size_t)(mi * 16 + g) * ostride + col);
                __half2 u1 = *(const __half2*)(ybase + (size_t)(mi * 16 + g + 8) * ostride + col);
                float2 f0 = __half22float2(u0), f1 = __half22float2(u1);
                acc[mi][ni][0] = f0.x; acc[mi][ni][1] = f0.y;
                acc[mi][ni][2] = f1.x; acc[mi][ni][3] = f1.y;
            } else {
                acc[mi][ni][0] = acc[mi][ni][1] = acc[mi][ni][2] = acc[mi][ni][3] = 0.f;
            }
        }

    // Stage W1 (2x384) and the 32 x-rows (each 384 floats) into smem.
    sW1[tid] = W1[tid];
    sW1[tid + 384] = W1[tid + 384];
    int rg = tid / 96, c4 = tid % 96;
#pragma unroll
    for (int it = 0; it < 8; it++) {
        int j = rg * 8 + it;
        int hh = which ? j : s;
        int ww = which ? s : j;
        const float4* src = (const float4*)(x + ((size_t)(b * 32 + hh) * 32 + ww) * ND);
        ((float4*)(sX + j * SXST))[c4] = src[c4];
    }
    __syncthreads();

    // which=0 blocks cover every x row exactly once across the grid:
    // emit the fp16 copy of x for the GEMM while it's in smem.
    if (!which) {
        __half* xh = g_xh + (size_t)blk * (32 * ND);
#pragma unroll
        for (int it = 0; it < 16; it++) {
            int idx = tid + it * 384;        // 32*192 half2 elements
            int j = idx / 192, p = idx % 192;
            float2 v = *(const float2*)(sX + j * SXST + 2 * p);
            *(__half2*)(xh + (size_t)j * ND + 2 * p) = __floats2half2_rn(v.x, v.y);
        }
    }

    // Projection: sY[e*32 + j] = dot(sX[j], W1[e]) + b1[e]
    for (int j = warp; j < 32; j += 12) {
        float p0 = 0.f, p1 = 0.f;
        const float* xr = sX + j * SXST;
#pragma unroll
        for (int q = 0; q < 12; q++) {
            float xv = xr[lane + 32 * q];
            p0 += xv * sW1[lane + 32 * q];
            p1 += xv * sW1[384 + lane + 32 * q];
        }
#pragma unroll
        for (int off = 16; off; off >>= 1) {
            p0 += __shfl_xor_sync(~0u, p0, off);
            p1 += __shfl_xor_sync(~0u, p1, off);
        }
        if (lane == 0) { sY[j] = p0 + b1[0]; sY[32 + j] = p1 + b1[1]; }
    }
    __syncthreads();

    // Grouped-mix logits: sZ[i][j] for t = i*32+j
    for (int t = tid; t < 1024; t += 384) {
        int i = t >> 5, j = t & 31;
        int grp = t >> 7;
        const float* yg = sY + grp * 8;
        float4 w0 = *(const float4*)(W2 + t * 8);
        float4 w1 = *(const float4*)(W2 + t * 8 + 4);
        sZ[i * SZST + j] = b2[t]
            + yg[0] * w0.x + yg[1] * w0.y + yg[2] * w0.z + yg[3] * w0.w
            + yg[4] * w1.x + yg[5] * w1.y + yg[6] * w1.z + yg[7] * w1.w;
    }
    __syncthreads();

    // Row softmax (over j), in place.
    for (int i = warp; i < 32; i += 12) {
        float v = sZ[i * SZST + lane];
        float m = v;
#pragma unroll
        for (int off = 16; off; off >>= 1) m = fmaxf(m, __shfl_xor_sync(~0u, m, off));
        float e = __expf(v - m);
        float su = e;
#pragma unroll
        for (int off = 16; off; off >>= 1) su += __shfl_xor_sync(~0u, su, off);
        sZ[i * SZST + lane] = e * (1.0f / su);
    }
    __syncthreads();

    // Tensor-core apply: Y[32,384] (+)= attn[32,32] @ X[32,384].
#pragma unroll
    for (int ks = 0; ks < 4; ks++) {
        int k0 = ks * 8;
        uint32_t a[2][4];
#pragma unroll
        for (int mi = 0; mi < 2; mi++) {
            int row = mi * 16 + g;
            a[mi][0] = f2tf(sZ[row * SZST + k0 + c]);
            a[mi][1] = f2tf(sZ[(row + 8) * SZST + k0 + c]);
            a[mi][2] = f2tf(sZ[row * SZST + k0 + c + 4]);
            a[mi][3] = f2tf(sZ[(row + 8) * SZST + k0 + c + 4]);
        }
        uint32_t bb[4][2];
#pragma unroll
        for (int ni = 0; ni < 4; ni++) {
            bb[ni][0] = f2tf(sX[(k0 + c) * SXST + dbase + ni * 8 + g]);
            bb[ni][1] = f2tf(sX[(k0 + c + 4) * SXST + dbase + ni * 8 + g]);
        }
#pragma unroll
        for (int mi = 0; mi < 2; mi++)
#pragma unroll
            for (int ni = 0; ni < 4; ni++)
                mma1688(acc[mi][ni], a[mi], bb[ni]);
    }

    // Epilogue: fp16 stores.
#pragma unroll
    for (int mi = 0; mi < 2; mi++)
#pragma unroll
        for (int ni = 0; ni < 4; ni++) {
            int col = dbase + ni * 8 + 2 * c;
            *(__half2*)(ybase + (size_t)(mi * 16 + g) * ostride + col) =
                __floats2half2_rn(acc[mi][ni][0], acc[mi][ni][1]);
            *(__half2*)(ybase + (size_t)(mi * 16 + g + 8) * ostride + col) =
                __floats2half2_rn(acc[mi][ni][2], acc[mi][ni][3]);
        }
}

// ---------------------------------------------------------------------------
// Final fused GEMM via mma.sync fp16 m16n8k16 on fp16-in-memory operands.
// out[m,o] = sum_d Yhw[m,d]*Wo[o,d] + sum_d x[m,d]*Wco[o,d] + bias[o]
// CTA tile 128x128, 8 warps 2(M)x4(N), warp tile 64x32 (proven optimal shape),
// BK=16, 4-stage cp.async ring, ONE barrier per chunk.
#define HW 20                        // smem row stride in 32-bit words (80B)
#define GSTG (2 * 128 * HW)          // uint32 words per stage (A then B)
#define G_DYN (4 * GSTG * 4)         // 4 stages -> 81920 bytes

__global__ __launch_bounds__(256, 2) void gemm_mma_kernel(float* __restrict__ out) {
    extern __shared__ uint32_t gsm[];

    int tid = threadIdx.x;
    int lane = tid & 31, warp = tid >> 5;
    int wm = warp >> 2, wn = warp & 3;       // warp coords: 2 x 4
    int g = lane >> 2, c = lane & 3;         // groupID, threadID_in_group
    int m0 = blockIdx.y * 128;
    int n0 = blockIdx.x * 128;

    float acc[4][4][4];
#pragma unroll
    for (int mi = 0; mi < 4; mi++)
#pragma unroll
        for (int ni = 0; ni < 4; ni++)
#pragma unroll
            for (int r = 0; r < 4; r++) acc[mi][ni][r] = 0.f;

    // chunk ch (0..47): K=768 over two phases; 16 halves (32B) per row per chunk.
    auto load_chunk = [&](int ch, int stg) {
        const __half* A; const __half* B; int ko;
        if (ch < 24) { A = g_Yhw_h + (size_t)m0 * ND; B = g_Wo_h  + (size_t)n0 * ND; ko = ch * 16; }
        else         { A = g_xh    + (size_t)m0 * ND; B = g_Wco_h + (size_t)n0 * ND; ko = ch * 16 - 384; }
        int row = tid >> 1, seg = tid & 1;
        uint32_t ab = s2u(gsm + stg * GSTG);
        uint32_t off = row * (HW * 4) + seg * 16;
        cp16(ab + off, A + (size_t)row * ND + ko + seg * 8);
        cp16(ab + 128 * HW * 4 + off, B + (size_t)row * ND + ko + seg * 8);
        asm volatile("cp.async.commit_group;" ::: "memory");
    };

    load_chunk(0, 0);
    load_chunk(1, 1);
    load_chunk(2, 2);

#pragma unroll 1
    for (int i = 0; i < 48; i++) {
        if (i + 2 < 48)      asm volatile("cp.async.wait_group 2;" ::: "memory");
        else if (i + 1 < 48) asm volatile("cp.async.wait_group 1;" ::: "memory");
        else                 asm volatile("cp.async.wait_group 0;" ::: "memory");
        __syncthreads();
        if (i + 3 < 48) load_chunk(i + 3, (i + 3) & 3);

        const uint32_t* pA = gsm + (i & 3) * GSTG;
        const uint32_t* pB = pA + 128 * HW;
        uint32_t afr[4][4];
#pragma unroll
        for (int mi = 0; mi < 4; mi++) {
            int r0 = (wm * 64 + mi * 16 + g) * HW + c;
            afr[mi][0] = pA[r0];
            afr[mi][1] = pA[r0 + 8 * HW];
            afr[mi][2] = pA[r0 + 4];
            afr[mi][3] = pA[r0 + 8 * HW + 4];
        }
        uint32_t bfr[4][2];
#pragma unroll
        for (int ni = 0; ni < 4; ni++) {
            int r0 = (wn * 32 + ni * 8 + g) * HW + c;
            bfr[ni][0] = pB[r0];
            bfr[ni][1] = pB[r0 + 4];
        }
#pragma unroll
        for (int mi = 0; mi < 4; mi++)
#pragma unroll
            for (int ni = 0; ni < 4; ni++)
                mma16816(acc[mi][ni], afr[mi], bfr[ni]);
    }

    // Epilogue: D layout m16n8: c0/c1 at (g, 2c/2c+1), c2/c3 at (g+8, ...)
#pragma unroll
    for (int ni = 0; ni < 4; ni++) {
        int col = n0 + wn * 32 + ni * 8 + 2 * c;
        float b0 = g_bias[col], b1 = g_bias[col + 1];
#pragma unroll
        for (int mi = 0; mi < 4; mi++) {
            int row = m0 + wm * 64 + mi * 16 + g;
            float2 v0 = {acc[mi][ni][0] + b0, acc[mi][ni][1] + b1};
            float2 v1 = {acc[mi][ni][2] + b0, acc[mi][ni][3] + b1};
            *(float2*)(out + (size_t)row * ND + col) = v0;
            *(float2*)(out + (size_t)(row + 8) * ND + col) = v1;
        }
    }
}

// ---------------------------------------------------------------------------
extern "C" void kernel_launch(void* const* d_in, const int* in_sizes, int n_in,
                              void* d_out, int out_size) {
    const float* x   = (const float*)d_in[0];
    const float* Wc  = (const float*)d_in[1];
    const float* bc  = (const float*)d_in[2];
    const float* Wo  = (const float*)d_in[3];
    const float* bo  = (const float*)d_in[4];
    const float* W1h = (const float*)d_in[5];
    const float* b1h = (const float*)d_in[6];
    const float* W2h = (const float*)d_in[7];
    const float* b2h = (const float*)d_in[8];
    const float* W1w = (const float*)d_in[9];
    const float* b1w = (const float*)d_in[10];
    const float* W2w = (const float*)d_in[11];
    const float* b2w = (const float*)d_in[12];
    float* out = (float*)d_out;

    static int attr_set = 0;
    if (!attr_set) {
        cudaFuncSetAttribute(mix_fused_kernel, cudaFuncAttributeMaxDynamicSharedMemorySize, MX_DYN);
        cudaFuncSetAttribute(gemm_mma_kernel, cudaFuncAttributeMaxDynamicSharedMemorySize, G_DYN);
        attr_set = 1;
    }

    wco_kernel<<<dim3(24, 24), dim3(16, 16)>>>(Wo, Wc);
    bias_kernel<<<ND / 32, 1024>>>(Wo, bc, bo);
    convw_kernel<<<ND * ND / 1024, 1024>>>(Wo);
    // which=0: w-mix (block (b,h)), writes Yhw_h + emits g_xh
    mix_fused_kernel<<<NB * NH, 384, MX_DYN>>>(x, W1w, b1w, W2w, b2w, 0);
    // which=1: h-mix (block (b,w)), accumulates into Yhw_h
    mix_fused_kernel<<<NB * NW, 384, MX_DYN>>>(x, W1h, b1h, W2h, b2h, 1);
    gemm_mma_kernel<<<dim3(ND / 128, NBHW / 128), 256, G_DYN>>>(out);
}

// round 16
// speedup vs baseline: 1.5113x; 1.5113x over previous
#include <cuda_runtime.h>
#include <cuda_fp16.h>
#include <cstdint>

// Problem constants
#define NB   64
#define NH   32
#define NW   32
#define ND   384
#define NBHW (NB*NH*NW)          // 65536 rows

// Scratch (device globals; no allocation allowed)
__device__ __half g_Yhw_h[(size_t)NBHW * ND];   // Yh + Yw (fp16)
__device__ __half g_xh[(size_t)NBHW * ND];      // fp16 copy of x
__device__ __half g_Wo_h[ND * ND];              // fp16 Wo
__device__ __half g_Wco_h[ND * ND];             // fp16 (Wo @ Wc)
__device__ float  g_bias[ND];                   // Wo @ bc + bo

static __device__ __forceinline__ uint32_t s2u(const void* p) {
    uint32_t a;
    asm("{ .reg .u64 t; cvta.to.shared.u64 t, %1; cvt.u32.u64 %0, t; }" : "=r"(a) : "l"(p));
    return a;
}
static __device__ __forceinline__ void cp16(uint32_t dst, const void* src) {
    asm volatile("cp.async.cg.shared.global [%0], [%1], 16;" :: "r"(dst), "l"(src));
}
static __device__ __forceinline__ uint32_t f2tf(float f) {
    uint32_t r;
    asm("cvt.rna.tf32.f32 %0, %1;" : "=r"(r) : "f"(f));
    return r;
}
static __device__ __forceinline__ void mma1688(float* d, const uint32_t* a, const uint32_t* b) {
    asm volatile(
        "mma.sync.aligned.m16n8k8.row.col.f32.tf32.tf32.f32 "
        "{%0,%1,%2,%3},{%4,%5,%6,%7},{%8,%9},{%0,%1,%2,%3};"
        : "+f"(d[0]), "+f"(d[1]), "+f"(d[2]), "+f"(d[3])
        : "r"(a[0]), "r"(a[1]), "r"(a[2]), "r"(a[3]), "r"(b[0]), "r"(b[1]));
}
static __device__ __forceinline__ void mma16816(float* d, const uint32_t* a, const uint32_t* b) {
    asm volatile(
        "mma.sync.aligned.m16n8k16.row.col.f32.f16.f16.f32 "
        "{%0,%1,%2,%3},{%4,%5,%6,%7},{%8,%9},{%0,%1,%2,%3};"
        : "+f"(d[0]), "+f"(d[1]), "+f"(d[2]), "+f"(d[3])
        : "r"(a[0]), "r"(a[1]), "r"(a[2]), "r"(a[3]), "r"(b[0]), "r"(b[1]));
}

// ---------------------------------------------------------------------------
// Wco[o][d] = sum_k Wo[o][k] * Wc[k][d]  (stored fp16)
__global__ void wco_kernel(const float* __restrict__ Wo, const float* __restrict__ Wc) {
    __shared__ float As[16][16];
    __shared__ float Bs[16][17];
    int o = blockIdx.y * 16 + threadIdx.y;
    int d = blockIdx.x * 16 + threadIdx.x;
    float acc = 0.f;
    for (int k0 = 0; k0 < ND; k0 += 16) {
        As[threadIdx.y][threadIdx.x] = Wo[o * ND + k0 + threadIdx.x];
        Bs[threadIdx.y][threadIdx.x] = Wc[(k0 + threadIdx.y) * ND + d];
        __syncthreads();
#pragma unroll
        for (int k = 0; k < 16; k++) acc += As[threadIdx.y][k] * Bs[k][threadIdx.x];
        __syncthreads();
    }
    g_Wco_h[o * ND + d] = __float2half(acc);
}

// bias[o] = bo[o] + sum_k Wo[o][k]*bc[k] — one warp per output element.
__global__ void bias_kernel(const float* __restrict__ Wo, const float* __restrict__ bc,
                            const float* __restrict__ bo) {
    int warp = threadIdx.x >> 5, lane = threadIdx.x & 31;
    int o = blockIdx.x * 32 + warp;
    float s = 0.f;
#pragma unroll
    for (int q = 0; q < 12; q++)
        s += Wo[o * ND + lane + 32 * q] * bc[lane + 32 * q];
#pragma unroll
    for (int off = 16; off; off >>= 1) s += __shfl_xor_sync(~0u, s, off);
    if (lane == 0) g_bias[o] = s + bo[o];
}

// Wo -> fp16
__global__ void convw_kernel(const float* __restrict__ Wo) {
    int idx = blockIdx.x * 1024 + threadIdx.x;
    g_Wo_h[idx] = __float2half(Wo[idx]);
}

// ---------------------------------------------------------------------------
// Fully fused mixer pass: projection + grouped-mix logits + softmax + tensor-core apply.
// which=0 (w-mix): block (b, h=s): rows j = w, reads fp32 x; writes Yhw_h; emits g_xh.
// which=1 (h-mix): block (b, w=s): rows j = h, reads g_xh (fp16); accumulates into Yhw_h.
// smem floats: sX[32][388] | sW1[768] | sY[64] | sZ[32][36]
#define SXST  388
#define SZST  36
#define MX_SX   0
#define MX_SW1  (32 * SXST)
#define MX_SY   (MX_SW1 + 768)
#define MX_SZ   (MX_SY + 64)
#define MX_DYN  ((MX_SZ + 32 * SZST) * 4)   // 57,600 bytes

__global__ __launch_bounds__(384, 2) void mix_fused_kernel(
    const float* __restrict__ x, const float* __restrict__ W1,
    const float* __restrict__ b1, const float* __restrict__ W2,
    const float* __restrict__ b2, int which) {
    extern __shared__ float sm[];
    float* sX  = sm + MX_SX;
    float* sW1 = sm + MX_SW1;
    float* sY  = sm + MX_SY;
    float* sZ  = sm + MX_SZ;

    int tid = threadIdx.x;
    int blk = blockIdx.x;
    int b = blk >> 5, s = blk & 31;
    int warp = tid >> 5, lane = tid & 31;
    int g = lane >> 2, c = lane & 3;
    int dbase = warp * 32;                   // this warp's 32 output columns

    __half* ybase;
    size_t ostride;
    if (which) { ybase = g_Yhw_h + ((size_t)b * 1024 + s) * ND; ostride = (size_t)32 * ND; }
    else       { ybase = g_Yhw_h + (size_t)blk * (32 * ND);     ostride = (size_t)ND; }

    // MMA accumulators; which=1 preloads its RMW values now (latency hidden
    // behind staging / proj / softmax below).
    float acc[2][4][4];
#pragma unroll
    for (int mi = 0; mi < 2; mi++)
#pragma unroll
        for (int ni = 0; ni < 4; ni++) {
            if (which) {
                int col = dbase + ni * 8 + 2 * c;
                __half2 u0 = *(const __half2*)(ybase + (size_t)(mi * 16 + g) * ostride + col);
                __half2 u1 = *(const __half2*)(ybase + (size_t)(mi * 16 + g + 8) * ostride + col);
                float2 f0 = __half22float2(u0), f1 = __half22float2(u1);
                acc[mi][ni][0] = f0.x; acc[mi][ni][1] = f0.y;
                acc[mi][ni][2] = f1.x; acc[mi][ni][3] = f1.y;
            } else {
                acc[mi][ni][0] = acc[mi][ni][1] = acc[mi][ni][2] = acc[mi][ni][3] = 0.f;
            }
        }

    // Stage W1 (2x384) and the 32 x-rows (each 384 floats) into smem.
    sW1[tid] = W1[tid];
    sW1[tid + 384] = W1[tid + 384];
    int rg = tid / 96, c4 = tid % 96;
    if (which) {
        // fp16 source (g_xh written by the which=0 pass): halves the x traffic.
#pragma unroll
        for (int it = 0; it < 8; it++) {
            int j = rg * 8 + it;
            const uint2* src = (const uint2*)(g_xh + ((size_t)(b * 32 + j) * 32 + s) * ND);
            uint2 v = src[c4];
            float2 f0 = __half22float2(*(const __half2*)&v.x);
            float2 f1 = __half22float2(*(const __half2*)&v.y);
            float4 st = {f0.x, f0.y, f1.x, f1.y};
            ((float4*)(sX + j * SXST))[c4] = st;
        }
    } else {
#pragma unroll
        for (int it = 0; it < 8; it++) {
            int j = rg * 8 + it;
            const float4* src = (const float4*)(x + ((size_t)(b * 32 + s) * 32 + j) * ND);
            ((float4*)(sX + j * SXST))[c4] = src[c4];
        }
    }
    __syncthreads();

    // which=0 blocks cover every x row exactly once across the grid:
    // emit the fp16 copy of x for the GEMM (and the which=1 pass).
    if (!which) {
        __half* xh = g_xh + (size_t)blk * (32 * ND);
#pragma unroll
        for (int it = 0; it < 16; it++) {
            int idx = tid + it * 384;        // 32*192 half2 elements
            int j = idx / 192, p = idx % 192;
            float2 v = *(const float2*)(sX + j * SXST + 2 * p);
            *(__half2*)(xh + (size_t)j * ND + 2 * p) = __floats2half2_rn(v.x, v.y);
        }
    }

    // Projection: sY[e*32 + j] = dot(sX[j], W1[e]) + b1[e]
    for (int j = warp; j < 32; j += 12) {
        float p0 = 0.f, p1 = 0.f;
        const float* xr = sX + j * SXST;
#pragma unroll
        for (int q = 0; q < 12; q++) {
            float xv = xr[lane + 32 * q];
            p0 += xv * sW1[lane + 32 * q];
            p1 += xv * sW1[384 + lane + 32 * q];
        }
#pragma unroll
        for (int off = 16; off; off >>= 1) {
            p0 += __shfl_xor_sync(~0u, p0, off);
            p1 += __shfl_xor_sync(~0u, p1, off);
        }
        if (lane == 0) { sY[j] = p0 + b1[0]; sY[32 + j] = p1 + b1[1]; }
    }
    __syncthreads();

    // Grouped-mix logits: sZ[i][j] for t = i*32+j
    for (int t = tid; t < 1024; t += 384) {
        int i = t >> 5, j = t & 31;
        int grp = t >> 7;
        const float* yg = sY + grp * 8;
        float4 w0 = *(const float4*)(W2 + t * 8);
        float4 w1 = *(const float4*)(W2 + t * 8 + 4);
        sZ[i * SZST + j] = b2[t]
            + yg[0] * w0.x + yg[1] * w0.y + yg[2] * w0.z + yg[3] * w0.w
            + yg[4] * w1.x + yg[5] * w1.y + yg[6] * w1.z + yg[7] * w1.w;
    }
    __syncthreads();

    // Row softmax (over j), in place.
    for (int i = warp; i < 32; i += 12) {
        float v = sZ[i * SZST + lane];
        float m = v;
#pragma unroll
        for (int off = 16; off; off >>= 1) m = fmaxf(m, __shfl_xor_sync(~0u, m, off));
        float e = __expf(v - m);
        float su = e;
#pragma unroll
        for (int off = 16; off; off >>= 1) su += __shfl_xor_sync(~0u, su, off);
        sZ[i * SZST + lane] = e * (1.0f / su);
    }
    __syncthreads();

    // Tensor-core apply: Y[32,384] (+)= attn[32,32] @ X[32,384].
#pragma unroll
    for (int ks = 0; ks < 4; ks++) {
        int k0 = ks * 8;
        uint32_t a[2][4];
#pragma unroll
        for (int mi = 0; mi < 2; mi++) {
            int row = mi * 16 + g;
            a[mi][0] = f2tf(sZ[row * SZST + k0 + c]);
            a[mi][1] = f2tf(sZ[(row + 8) * SZST + k0 + c]);
            a[mi][2] = f2tf(sZ[row * SZST + k0 + c + 4]);
            a[mi][3] = f2tf(sZ[(row + 8) * SZST + k0 + c + 4]);
        }
        uint32_t bb[4][2];
#pragma unroll
        for (int ni = 0; ni < 4; ni++) {
            bb[ni][0] = f2tf(sX[(k0 + c) * SXST + dbase + ni * 8 + g]);
            bb[ni][1] = f2tf(sX[(k0 + c + 4) * SXST + dbase + ni * 8 + g]);
        }
#pragma unroll
        for (int mi = 0; mi < 2; mi++)
#pragma unroll
            for (int ni = 0; ni < 4; ni++)
                mma1688(acc[mi][ni], a[mi], bb[ni]);
    }

    // Epilogue: fp16 stores.
#pragma unroll
    for (int mi = 0; mi < 2; mi++)
#pragma unroll
        for (int ni = 0; ni < 4; ni++) {
            int col = dbase + ni * 8 + 2 * c;
            *(__half2*)(ybase + (size_t)(mi * 16 + g) * ostride + col) =
                __floats2half2_rn(acc[mi][ni][0], acc[mi][ni][1]);
            *(__half2*)(ybase + (size_t)(mi * 16 + g + 8) * ostride + col) =
                __floats2half2_rn(acc[mi][ni][2], acc[mi][ni][3]);
        }
}

// ---------------------------------------------------------------------------
// Final fused GEMM via mma.sync fp16 m16n8k16 on fp16-in-memory operands.
// out[m,o] = sum_d Yhw[m,d]*Wo[o,d] + sum_d x[m,d]*Wco[o,d] + bias[o]
// CTA tile 128x128, 8 warps 2(M)x4(N), warp tile 64x32, BK=16, double buffer.
// (R13 configuration — frozen; every variation tried regressed.)
#define HW 20   // smem row stride in 32-bit words (80B): conflict-free frags

__global__ __launch_bounds__(256, 2) void gemm_mma_kernel(float* __restrict__ out) {
    __shared__ uint32_t sA[2][128 * HW];
    __shared__ uint32_t sB[2][128 * HW];

    int tid = threadIdx.x;
    int lane = tid & 31, warp = tid >> 5;
    int wm = warp >> 2, wn = warp & 3;       // warp coords: 2 x 4
    int g = lane >> 2, c = lane & 3;         // groupID, threadID_in_group
    int m0 = blockIdx.y * 128;
    int n0 = blockIdx.x * 128;

    float acc[4][4][4];
#pragma unroll
    for (int mi = 0; mi < 4; mi++)
#pragma unroll
        for (int ni = 0; ni < 4; ni++)
#pragma unroll
            for (int r = 0; r < 4; r++) acc[mi][ni][r] = 0.f;

    // chunk ch (0..47): K=768 over two phases; 16 halves (32B) per row per chunk.
    auto load_chunk = [&](int ch, int buf) {
        const __half* A; const __half* B; int ko;
        if (ch < 24) { A = g_Yhw_h + (size_t)m0 * ND; B = g_Wo_h  + (size_t)n0 * ND; ko = ch * 16; }
        else         { A = g_xh    + (size_t)m0 * ND; B = g_Wco_h + (size_t)n0 * ND; ko = ch * 16 - 384; }
        int row = tid >> 1, seg = tid & 1;
        uint32_t off = row * (HW * 4) + seg * 16;
        cp16(s2u(&sA[buf][0]) + off, A + (size_t)row * ND + ko + seg * 8);
        cp16(s2u(&sB[buf][0]) + off, B + (size_t)row * ND + ko + seg * 8);
        asm volatile("cp.async.commit_group;" ::: "memory");
    };

    load_chunk(0, 0);

#pragma unroll 1
    for (int i = 0; i < 48; i++) {
        int buf = i & 1;
        if (i + 1 < 48) load_chunk(i + 1, buf ^ 1);
        if (i + 1 < 48) asm volatile("cp.async.wait_group 1;" ::: "memory");
        else            asm volatile("cp.async.wait_group 0;" ::: "memory");
        __syncthreads();

        const uint32_t* pA = &sA[buf][0];
        const uint32_t* pB = &sB[buf][0];
        uint32_t afr[4][4];
#pragma unroll
        for (int mi = 0; mi < 4; mi++) {
            int r0 = (wm * 64 + mi * 16 + g) * HW + c;
            afr[mi][0] = pA[r0];
            afr[mi][1] = pA[r0 + 8 * HW];
            afr[mi][2] = pA[r0 + 4];
            afr[mi][3] = pA[r0 + 8 * HW + 4];
        }
        uint32_t bfr[4][2];
#pragma unroll
        for (int ni = 0; ni < 4; ni++) {
            int r0 = (wn * 32 + ni * 8 + g) * HW + c;
            bfr[ni][0] = pB[r0];
            bfr[ni][1] = pB[r0 + 4];
        }
#pragma unroll
        for (int mi = 0; mi < 4; mi++)
#pragma unroll
            for (int ni = 0; ni < 4; ni++)
                mma16816(acc[mi][ni], afr[mi], bfr[ni]);
        __syncthreads();
    }

    // Epilogue: D layout m16n8: c0/c1 at (g, 2c/2c+1), c2/c3 at (g+8, ...)
#pragma unroll
    for (int ni = 0; ni < 4; ni++) {
        int col = n0 + wn * 32 + ni * 8 + 2 * c;
        float b0 = g_bias[col], b1 = g_bias[col + 1];
#pragma unroll
        for (int mi = 0; mi < 4; mi++) {
            int row = m0 + wm * 64 + mi * 16 + g;
            float2 v0 = {acc[mi][ni][0] + b0, acc[mi][ni][1] + b1};
            float2 v1 = {acc[mi][ni][2] + b0, acc[mi][ni][3] + b1};
            *(float2*)(out + (size_t)row * ND + col) = v0;
            *(float2*)(out + (size_t)(row + 8) * ND + col) = v1;
        }
    }
}

// ---------------------------------------------------------------------------
extern "C" void kernel_launch(void* const* d_in, const int* in_sizes, int n_in,
                              void* d_out, int out_size) {
    const float* x   = (const float*)d_in[0];
    const float* Wc  = (const float*)d_in[1];
    const float* bc  = (const float*)d_in[2];
    const float* Wo  = (const float*)d_in[3];
    const float* bo  = (const float*)d_in[4];
    const float* W1h = (const float*)d_in[5];
    const float* b1h = (const float*)d_in[6];
    const float* W2h = (const float*)d_in[7];
    const float* b2h = (const float*)d_in[8];
    const float* W1w = (const float*)d_in[9];
    const float* b1w = (const float*)d_in[10];
    const float* W2w = (const float*)d_in[11];
    const float* b2w = (const float*)d_in[12];
    float* out = (float*)d_out;

    static int attr_set = 0;
    if (!attr_set) {
        cudaFuncSetAttribute(mix_fused_kernel, cudaFuncAttributeMaxDynamicSharedMemorySize, MX_DYN);
        attr_set = 1;
    }

    wco_kernel<<<dim3(24, 24), dim3(16, 16)>>>(Wo, Wc);
    bias_kernel<<<ND / 32, 1024>>>(Wo, bc, bo);
    convw_kernel<<<ND * ND / 1024, 1024>>>(Wo);
    // which=0: w-mix (block (b,h)), reads fp32 x, writes Yhw_h + emits g_xh
    mix_fused_kernel<<<NB * NH, 384, MX_DYN>>>(x, W1w, b1w, W2w, b2w, 0);
    // which=1: h-mix (block (b,w)), reads g_xh, accumulates into Yhw_h
    mix_fused_kernel<<<NB * NW, 384, MX_DYN>>>(x, W1h, b1h, W2h, b2h, 1);
    gemm_mma_kernel<<<dim3(ND / 128, NBHW / 128), 256>>>(out);
}